// round 1
// baseline (speedup 1.0000x reference)
#include <cuda_runtime.h>

// Problem constants (fixed by the reference)
#define BB 2
#define LL 2048
#define HH 16
#define EE 64
#define STR 68            // smem row stride (floats): 272B, 16B-aligned rows, conflict-friendly
#define NTILE 32          // L / 64 key tiles

// Scratch for pre-RoPE'd Q and K (allocation-free: __device__ globals)
__device__ float g_Qr[BB * LL * HH * EE];
__device__ float g_Kr[BB * LL * HH * EE];

// ---------------------------------------------------------------------------
// Pre-pass: apply RoPE to Q and K once.  One thread per float4.
// theta_i = 10000^(-i/16) = exp2(-i * log2(10000)/16), pair i in [0,16)
// rope pair (x0,x1) -> (c*x0 - s*x1, c*x1 + s*x0), c/s at angle l*theta_i
// ---------------------------------------------------------------------------
__global__ void rope_kernel(const float* __restrict__ q,
                            const float* __restrict__ k) {
    int idx = blockIdx.x * blockDim.x + threadIdx.x;  // float4 index
    const int N4 = BB * LL * HH * (EE / 4);
    if (idx >= N4) return;
    int e4  = idx & 15;        // which float4 within the 64-dim head
    int row = idx >> 4;        // (b*L + l)*H + h
    float4 vq = ((const float4*)q)[idx];
    float4 vk = ((const float4*)k)[idx];
    if (e4 < 8) {              // first 32 dims get rotated
        int l = (row >> 4) & (LL - 1);          // row / H  mod L   (H = 16)
        float i0 = (float)(e4 * 2);             // pair index of .x/.y
        const float NEG_L2 = -0.83048202372184058696f;  // -log2(10000)/16
        float s0, c0, s1, c1;
        sincosf((float)l * exp2f(i0 * NEG_L2), &s0, &c0);
        sincosf((float)l * exp2f((i0 + 1.0f) * NEG_L2), &s1, &c1);
        float4 o;
        o.x = c0 * vq.x - s0 * vq.y;  o.y = c0 * vq.y + s0 * vq.x;
        o.z = c1 * vq.z - s1 * vq.w;  o.w = c1 * vq.w + s1 * vq.z;
        vq = o;
        o.x = c0 * vk.x - s0 * vk.y;  o.y = c0 * vk.y + s0 * vk.x;
        o.z = c1 * vk.z - s1 * vk.w;  o.w = c1 * vk.w + s1 * vk.z;
        vk = o;
    }
    ((float4*)g_Qr)[idx] = vq;
    ((float4*)g_Kr)[idx] = vk;
}

// ---------------------------------------------------------------------------
// Flash-attention over 64x64 tiles.
// Structure exploit: 64 = n_tokens, so each key tile is exactly one variable
// block -> bias is a per-tile scalar ((kt==qt) ? bw1[h] : bw0[h]) and the
// time mask is lower-triangular in LOCAL tile coordinates for EVERY tile.
// Block: 256 threads as 16x16, each owns a 4x4 microtile of the 64x64 S/O.
// ---------------------------------------------------------------------------
__global__ __launch_bounds__(256, 2)
void attn_kernel(const float* __restrict__ Vg_all,
                 const float* __restrict__ bw,
                 float* __restrict__ out) {
    __shared__ float Qs[64 * STR];   // [e][row]  (transposed for f4 frag loads)
    __shared__ float Ks[64 * STR];   // [e][col]
    __shared__ float Vs[64 * STR];   // [j][d]
    __shared__ float Ps[64 * STR];   // [j][row]  (transposed P)

    const int tid = threadIdx.x;
    const int tx = tid & 15;          // column group (4 cols)
    const int ty = tid >> 4;          // row group (4 rows)
    const int qt = blockIdx.x;        // query tile = query variable id
    const int h  = blockIdx.y;
    const int b  = blockIdx.z;
    const int l0 = qt * 64;

    const float* Qg = g_Qr + (size_t)b * (LL * HH * EE) + (size_t)h * EE;
    const float* Kg = g_Kr + (size_t)b * (LL * HH * EE) + (size_t)h * EE;
    const float* Vg = Vg_all + (size_t)b * (LL * HH * EE) + (size_t)h * EE;

    // ---- Load Q tile, transposed into smem [e][row] ----
    for (int t = tid; t < 64 * 16; t += 256) {
        int r = t >> 4, e = (t & 15) * 4;
        float4 v = *(const float4*)(Qg + (size_t)(l0 + r) * (HH * EE) + e);
        Qs[(e + 0) * STR + r] = v.x;
        Qs[(e + 1) * STR + r] = v.y;
        Qs[(e + 2) * STR + r] = v.z;
        Qs[(e + 3) * STR + r] = v.w;
    }

    float acc[4][4];
    #pragma unroll
    for (int i = 0; i < 4; i++)
        #pragma unroll
        for (int j = 0; j < 4; j++) acc[i][j] = 0.0f;
    float mrow[4] = {-1e30f, -1e30f, -1e30f, -1e30f};
    float lrow[4] = {0.0f, 0.0f, 0.0f, 0.0f};

    const float bias_same = bw[HH + h];
    const float bias_diff = bw[h];

    for (int kt = 0; kt < NTILE; kt++) {
        __syncthreads();   // previous PV done before tile overwrite
        const int s0 = kt * 64;
        // ---- Load K tile (transposed) and V tile ----
        for (int t = tid; t < 64 * 16; t += 256) {
            int r = t >> 4, e = (t & 15) * 4;
            float4 kv = *(const float4*)(Kg + (size_t)(s0 + r) * (HH * EE) + e);
            Ks[(e + 0) * STR + r] = kv.x;
            Ks[(e + 1) * STR + r] = kv.y;
            Ks[(e + 2) * STR + r] = kv.z;
            Ks[(e + 3) * STR + r] = kv.w;
            float4 vv = *(const float4*)(Vg + (size_t)(s0 + r) * (HH * EE) + e);
            *(float4*)&Vs[r * STR + e] = vv;
        }
        __syncthreads();

        // ---- S = Q K^T (64x64x64) ----
        float s[4][4];
        #pragma unroll
        for (int i = 0; i < 4; i++)
            #pragma unroll
            for (int j = 0; j < 4; j++) s[i][j] = 0.0f;

        #pragma unroll 16
        for (int e = 0; e < 64; e++) {
            float4 a  = *(const float4*)&Qs[e * STR + ty * 4];
            float4 bb = *(const float4*)&Ks[e * STR + tx * 4];
            float av[4] = {a.x, a.y, a.z, a.w};
            float bv[4] = {bb.x, bb.y, bb.z, bb.w};
            #pragma unroll
            for (int i = 0; i < 4; i++)
                #pragma unroll
                for (int j = 0; j < 4; j++)
                    s[i][j] = fmaf(av[i], bv[j], s[i][j]);
        }

        // ---- scale + bias + intra-tile triangular mask ----
        const float bias = (kt == qt) ? bias_same : bias_diff;
        #pragma unroll
        for (int i = 0; i < 4; i++) {
            int row = ty * 4 + i;
            #pragma unroll
            for (int j = 0; j < 4; j++) {
                int col = tx * 4 + j;
                float sv = fmaf(s[i][j], 0.125f, bias);
                s[i][j] = (col > row) ? -1e30f : sv;
            }
        }

        // ---- online softmax (row reductions across the 16 tx lanes) ----
        #pragma unroll
        for (int i = 0; i < 4; i++) {
            float m = fmaxf(fmaxf(s[i][0], s[i][1]), fmaxf(s[i][2], s[i][3]));
            #pragma unroll
            for (int o = 8; o >= 1; o >>= 1)
                m = fmaxf(m, __shfl_xor_sync(0xffffffffu, m, o));
            float mnew = fmaxf(mrow[i], m);
            float corr = __expf(mrow[i] - mnew);
            mrow[i] = mnew;
            float psum = 0.0f;
            #pragma unroll
            for (int j = 0; j < 4; j++) {
                float p = __expf(s[i][j] - mnew);
                s[i][j] = p;
                psum += p;
            }
            #pragma unroll
            for (int o = 8; o >= 1; o >>= 1)
                psum += __shfl_xor_sync(0xffffffffu, psum, o);
            lrow[i] = lrow[i] * corr + psum;
            #pragma unroll
            for (int j = 0; j < 4; j++) acc[i][j] *= corr;
        }

        // ---- stage P transposed: Ps[col][row] ----
        #pragma unroll
        for (int i = 0; i < 4; i++)
            #pragma unroll
            for (int j = 0; j < 4; j++)
                Ps[(tx * 4 + j) * STR + (ty * 4 + i)] = s[i][j];
        __syncthreads();

        // ---- O += P V (64x64x64) ----
        #pragma unroll 16
        for (int j = 0; j < 64; j++) {
            float4 p = *(const float4*)&Ps[j * STR + ty * 4];
            float4 v = *(const float4*)&Vs[j * STR + tx * 4];
            float pv[4] = {p.x, p.y, p.z, p.w};
            float vv[4] = {v.x, v.y, v.z, v.w};
            #pragma unroll
            for (int i = 0; i < 4; i++)
                #pragma unroll
                for (int d = 0; d < 4; d++)
                    acc[i][d] = fmaf(pv[i], vv[d], acc[i][d]);
        }
    }

    // ---- normalize and store (out layout: [b][l][h][d]) ----
    #pragma unroll
    for (int i = 0; i < 4; i++) {
        float inv = 1.0f / lrow[i];
        int row = l0 + ty * 4 + i;
        float4 o;
        o.x = acc[i][0] * inv;
        o.y = acc[i][1] * inv;
        o.z = acc[i][2] * inv;
        o.w = acc[i][3] * inv;
        *(float4*)(out + ((size_t)(b * LL + row) * HH + h) * EE + tx * 4) = o;
    }
}

// ---------------------------------------------------------------------------
extern "C" void kernel_launch(void* const* d_in, const int* in_sizes, int n_in,
                              void* d_out, int out_size) {
    const float* q  = (const float*)d_in[0];
    const float* k  = (const float*)d_in[1];
    const float* v  = (const float*)d_in[2];
    const float* bw = (const float*)d_in[3];
    float* out = (float*)d_out;

    const int N4 = BB * LL * HH * (EE / 4);
    rope_kernel<<<(N4 + 255) / 256, 256>>>(q, k);

    dim3 grid(NTILE, HH, BB);
    attn_kernel<<<grid, 256>>>(v, bw, out);
}

// round 3
// speedup vs baseline: 2.5517x; 2.5517x over previous
#include <cuda_runtime.h>
#include <cstdint>

#define BB 2
#define LL 2048
#define HH 16
#define EE 64
#define QM 128        // query rows per CTA
#define NKT 32        // 64-key tiles
#define STR 66        // smem row stride in floats (conflict-friendly)

__device__ float g_Qr[BB * LL * HH * EE];
__device__ float g_Kr[BB * LL * HH * EE];

// ---------------------------------------------------------------------------
// RoPE pre-pass (verified in round 1, rel_err 1e-6)
// ---------------------------------------------------------------------------
__global__ void rope_kernel(const float* __restrict__ q,
                            const float* __restrict__ k) {
    int idx = blockIdx.x * blockDim.x + threadIdx.x;
    const int N4 = BB * LL * HH * (EE / 4);
    if (idx >= N4) return;
    int e4  = idx & 15;
    int row = idx >> 4;
    float4 vq = ((const float4*)q)[idx];
    float4 vk = ((const float4*)k)[idx];
    if (e4 < 8) {
        int l = (row >> 4) & (LL - 1);
        float i0 = (float)(e4 * 2);
        const float NEG_L2 = -0.83048202372184058696f;  // -log2(10000)/16
        float s0, c0, s1, c1;
        sincosf((float)l * exp2f(i0 * NEG_L2), &s0, &c0);
        sincosf((float)l * exp2f((i0 + 1.0f) * NEG_L2), &s1, &c1);
        float4 o;
        o.x = c0 * vq.x - s0 * vq.y;  o.y = c0 * vq.y + s0 * vq.x;
        o.z = c1 * vq.z - s1 * vq.w;  o.w = c1 * vq.w + s1 * vq.z;
        vq = o;
        o.x = c0 * vk.x - s0 * vk.y;  o.y = c0 * vk.y + s0 * vk.x;
        o.z = c1 * vk.z - s1 * vk.w;  o.w = c1 * vk.w + s1 * vk.z;
        vk = o;
    }
    ((float4*)g_Qr)[idx] = vq;
    ((float4*)g_Kr)[idx] = vk;
}

// ---------------------------------------------------------------------------
// helpers
// ---------------------------------------------------------------------------
__device__ __forceinline__ uint32_t f2tf(float x) {
    uint32_t u;
    asm("cvt.rna.tf32.f32 %0, %1;" : "=r"(u) : "f"(x));
    return u;
}
__device__ __forceinline__ float ex2f(float x) {
    float o;
    asm("ex2.approx.f32 %0, %1;" : "=f"(o) : "f"(x));
    return o;
}
__device__ __forceinline__ void mma8(float c[4], const uint32_t a[4],
                                     uint32_t b0, uint32_t b1) {
    asm volatile(
        "mma.sync.aligned.m16n8k8.row.col.f32.tf32.tf32.f32 "
        "{%0,%1,%2,%3}, {%4,%5,%6,%7}, {%8,%9}, {%0,%1,%2,%3};"
        : "+f"(c[0]), "+f"(c[1]), "+f"(c[2]), "+f"(c[3])
        : "r"(a[0]), "r"(a[1]), "r"(a[2]), "r"(a[3]), "r"(b0), "r"(b1));
}

#define LOG2E 1.4426950408889634f
#define SCL2  0.18033688011112042592f   // 0.125 * log2(e)

// ---------------------------------------------------------------------------
// mma.sync tf32 flash attention.
// CTA: 128 threads (4 warps). Warp w owns query rows [w*32, w*32+32).
// Q A-frags persistent in regs; O accumulates in regs across all key tiles.
// K smem layout Ks[key][permdim]: dim d=kb*8+h*4+t stored at kb*8+t*2+h so
//   tf32 B-frag (b0=dim t, b1=dim t+4) is one LDS.64.
// V smem layout Vs[dim][permkey]: same permutation on the key index.
// P relayout C-frag -> A-frag via 8 quad-shuffles per (mb, kblock).
// No-max softmax: per-thread row sums only, reduced once at the end.
// ---------------------------------------------------------------------------
__global__ __launch_bounds__(128, 2)
void attn_mma(const float* __restrict__ Vg_all,
              const float* __restrict__ bw,
              float* __restrict__ out) {
    __shared__ float sm[2 * 64 * STR];          // Ks | Vs ; Q staging overlays
    float* Ks = sm;
    float* Vs = sm + 64 * STR;

    const int tid  = threadIdx.x;
    const int lane = tid & 31;
    const int w    = tid >> 5;
    const int g    = lane >> 2;      // group (row) id 0..7
    const int t    = lane & 3;       // thread-in-group 0..3
    const int base = lane & ~3;
    const int qtb  = blockIdx.x;
    const int h    = blockIdx.y;
    const int b    = blockIdx.z;
    const int l0   = qtb * QM;

    // ---- stage Q (tf32-converted) into smem, then load persistent A-frags ----
    const float* Qg = g_Qr + ((size_t)(b * LL + l0) * HH + h) * EE;
    for (int it = 0; it < 16; it++) {
        int idx = it * 128 + tid;
        int r = idx >> 4, e = (idx & 15) * 4;
        float4 v = *(const float4*)(Qg + (size_t)r * (HH * EE) + e);
        float* qd = sm + r * STR + e;
        qd[0] = __uint_as_float(f2tf(v.x));
        qd[1] = __uint_as_float(f2tf(v.y));
        qd[2] = __uint_as_float(f2tf(v.z));
        qd[3] = __uint_as_float(f2tf(v.w));
    }
    __syncthreads();

    uint32_t qa[2][8][4];
    #pragma unroll
    for (int mb = 0; mb < 2; mb++)
        #pragma unroll
        for (int kb = 0; kb < 8; kb++) {
            int r0 = (w * 32 + mb * 16 + g) * STR + kb * 8 + t;
            qa[mb][kb][0] = __float_as_uint(sm[r0]);
            qa[mb][kb][1] = __float_as_uint(sm[r0 + 8 * STR]);
            qa[mb][kb][2] = __float_as_uint(sm[r0 + 4]);
            qa[mb][kb][3] = __float_as_uint(sm[r0 + 8 * STR + 4]);
        }
    __syncthreads();

    float oacc[2][8][4];
    #pragma unroll
    for (int mb = 0; mb < 2; mb++)
        #pragma unroll
        for (int db = 0; db < 8; db++)
            #pragma unroll
            for (int i = 0; i < 4; i++) oacc[mb][db][i] = 0.0f;
    float lsum[2][2] = {{0.0f, 0.0f}, {0.0f, 0.0f}};

    const float b2s = bw[HH + h] * LOG2E;
    const float b2d = bw[h] * LOG2E;
    const int   qvar = qtb * 2 + (w >> 1);
    const int   rm[2] = { (w * 32 + g) & 63, (w * 32 + 16 + g) & 63 };
    const int   ce = 2 * t;      // even col within nblock (plus nb*8)
    const int   src0 = base + (t >> 1);
    const int   src1 = src0 + 2;
    const bool  odd  = (t & 1);

    const float* Kg0 = g_Kr  + ((size_t)(b * LL) * HH + h) * EE;
    const float* Vg0 = Vg_all + ((size_t)(b * LL) * HH + h) * EE;

    for (int kt = 0; kt < NKT; kt++) {
        __syncthreads();   // previous tile's PV reads done
        const float* Kg = Kg0 + (size_t)kt * 64 * (HH * EE);
        const float* Vg = Vg0 + (size_t)kt * 64 * (HH * EE);

        // ---- stage K (perm dims) and V (perm keys), tf32-converted ----
        for (int it = 0; it < 8; it++) {
            int idx = it * 128 + tid;
            int kr = idx >> 4, e = (idx & 15) * 4;
            float4 kv = *(const float4*)(Kg + (size_t)kr * (HH * EE) + e);
            float* kd = Ks + kr * STR + ((e & ~7) | ((e >> 2) & 1));
            kd[0] = __uint_as_float(f2tf(kv.x));
            kd[2] = __uint_as_float(f2tf(kv.y));
            kd[4] = __uint_as_float(f2tf(kv.z));
            kd[6] = __uint_as_float(f2tf(kv.w));
            float4 vv = *(const float4*)(Vg + (size_t)kr * (HH * EE) + e);
            int pk = (kr & ~7) | ((kr & 3) << 1) | ((kr >> 2) & 1);
            Vs[(e + 0) * STR + pk] = __uint_as_float(f2tf(vv.x));
            Vs[(e + 1) * STR + pk] = __uint_as_float(f2tf(vv.y));
            Vs[(e + 2) * STR + pk] = __uint_as_float(f2tf(vv.z));
            Vs[(e + 3) * STR + pk] = __uint_as_float(f2tf(vv.w));
        }
        __syncthreads();

        const float biasl = (kt == qvar) ? b2s : b2d;

        #pragma unroll
        for (int nb = 0; nb < 8; nb++) {
            // ---- S = Q K^T for this 8-col block ----
            float c[2][4] = {{0, 0, 0, 0}, {0, 0, 0, 0}};
            #pragma unroll
            for (int kb = 0; kb < 8; kb++) {
                uint2 bb = *(const uint2*)(Ks + (nb * 8 + g) * STR + kb * 8 + t * 2);
                mma8(c[0], qa[0][kb], bb.x, bb.y);
                mma8(c[1], qa[1][kb], bb.x, bb.y);
            }

            // ---- softmax (no max-subtract) + tf32 cvt + frag relayout ----
            uint32_t pa[2][4];
            const int c0i = nb * 8 + ce, c1i = c0i + 1;
            #pragma unroll
            for (int mb = 0; mb < 2; mb++) {
                const int r0 = rm[mb];
                float p0 = (c0i <= r0)     ? ex2f(fmaf(c[mb][0], SCL2, biasl)) : 0.0f;
                float p1 = (c1i <= r0)     ? ex2f(fmaf(c[mb][1], SCL2, biasl)) : 0.0f;
                float p2 = (c0i <= r0 + 8) ? ex2f(fmaf(c[mb][2], SCL2, biasl)) : 0.0f;
                float p3 = (c1i <= r0 + 8) ? ex2f(fmaf(c[mb][3], SCL2, biasl)) : 0.0f;
                lsum[mb][0] += p0 + p1;
                lsum[mb][1] += p2 + p3;
                uint32_t u0 = f2tf(p0), u1 = f2tf(p1), u2 = f2tf(p2), u3 = f2tf(p3);
                uint32_t x0 = __shfl_sync(0xffffffffu, u0, src0);
                uint32_t x1 = __shfl_sync(0xffffffffu, u1, src0);
                pa[mb][0] = odd ? x1 : x0;
                uint32_t y0 = __shfl_sync(0xffffffffu, u2, src0);
                uint32_t y1 = __shfl_sync(0xffffffffu, u3, src0);
                pa[mb][1] = odd ? y1 : y0;
                uint32_t z0 = __shfl_sync(0xffffffffu, u0, src1);
                uint32_t z1 = __shfl_sync(0xffffffffu, u1, src1);
                pa[mb][2] = odd ? z1 : z0;
                uint32_t w0 = __shfl_sync(0xffffffffu, u2, src1);
                uint32_t w1 = __shfl_sync(0xffffffffu, u3, src1);
                pa[mb][3] = odd ? w1 : w0;
            }

            // ---- O += P V, k-block = nb ----
            #pragma unroll
            for (int db = 0; db < 8; db++) {
                uint2 vb = *(const uint2*)(Vs + (db * 8 + g) * STR + nb * 8 + t * 2);
                mma8(oacc[0][db], pa[0], vb.x, vb.y);
                mma8(oacc[1][db], pa[1], vb.x, vb.y);
            }
        }
    }

    // ---- reduce row sums across the quad, normalize, store ----
    #pragma unroll
    for (int mb = 0; mb < 2; mb++)
        #pragma unroll
        for (int i = 0; i < 2; i++) {
            float v = lsum[mb][i];
            v += __shfl_xor_sync(0xffffffffu, v, 1);
            v += __shfl_xor_sync(0xffffffffu, v, 2);
            lsum[mb][i] = 1.0f / v;
        }

    #pragma unroll
    for (int mb = 0; mb < 2; mb++) {
        int r0 = l0 + w * 32 + mb * 16 + g;
        #pragma unroll
        for (int db = 0; db < 8; db++) {
            float2 v0;
            v0.x = oacc[mb][db][0] * lsum[mb][0];
            v0.y = oacc[mb][db][1] * lsum[mb][0];
            *(float2*)(out + (((size_t)(b * LL + r0)) * HH + h) * EE + db * 8 + 2 * t) = v0;
            float2 v1;
            v1.x = oacc[mb][db][2] * lsum[mb][1];
            v1.y = oacc[mb][db][3] * lsum[mb][1];
            *(float2*)(out + (((size_t)(b * LL + r0 + 8)) * HH + h) * EE + db * 8 + 2 * t) = v1;
        }
    }
}

// ---------------------------------------------------------------------------
extern "C" void kernel_launch(void* const* d_in, const int* in_sizes, int n_in,
                              void* d_out, int out_size) {
    const float* q  = (const float*)d_in[0];
    const float* k  = (const float*)d_in[1];
    const float* v  = (const float*)d_in[2];
    const float* bw = (const float*)d_in[3];
    float* out = (float*)d_out;

    const int N4 = BB * LL * HH * (EE / 4);
    rope_kernel<<<(N4 + 255) / 256, 256>>>(q, k);

    dim3 grid(LL / QM, HH, BB);
    attn_mma<<<grid, 128>>>(v, bw, out);
}

// round 4
// speedup vs baseline: 3.5478x; 1.3904x over previous
#include <cuda_runtime.h>
#include <cstdint>

#define BB 2
#define LL 2048
#define HH 16
#define EE 64
#define NKT 32

// Frag-ready preprocessed operands (tf32-rounded):
//  g_Qp[bh][l][pd], g_Kp[bh][l][pd]  with pd = frag-permuted dim
//  g_Vt[bh][d][pk]                   with pk = frag-permuted key (transposed V)
__device__ float g_Qp[BB * HH * LL * EE];
__device__ float g_Kp[BB * HH * LL * EE];
__device__ float g_Vt[BB * HH * EE * LL];

#define LOG2E 1.4426950408889634f
#define SCL2  0.18033688011112042592f   // 0.125 * log2(e)

__device__ __forceinline__ uint32_t f2tf(float x) {
    uint32_t u;
    asm("cvt.rna.tf32.f32 %0, %1;" : "=r"(u) : "f"(x));
    return u;
}
__device__ __forceinline__ float tfr(float x) { return __uint_as_float(f2tf(x)); }
__device__ __forceinline__ float ex2f(float x) {
    float o;
    asm("ex2.approx.f32 %0, %1;" : "=f"(o) : "f"(x));
    return o;
}
__device__ __forceinline__ void mma8(float c[4], const uint32_t a[4],
                                     uint32_t b0, uint32_t b1) {
    asm volatile(
        "mma.sync.aligned.m16n8k8.row.col.f32.tf32.tf32.f32 "
        "{%0,%1,%2,%3}, {%4,%5,%6,%7}, {%8,%9}, {%0,%1,%2,%3};"
        : "+f"(c[0]), "+f"(c[1]), "+f"(c[2]), "+f"(c[3])
        : "r"(a[0]), "r"(a[1]), "r"(a[2]), "r"(a[3]), "r"(b0), "r"(b1));
}

// frag permutation: d = kb*8 + u*4 + t  ->  (kb>>1)*16 + t*4 + (kb&1)*2 + u
// so one LDG.128 at (kbp*16 + t*4) yields b-frags (t, t+4) for kb=2kbp, 2kbp+1.
__device__ __forceinline__ int permd(int d) {
    return ((d >> 4) << 4) + (d & 3) * 4 + ((d >> 3) & 1) * 2 + ((d >> 2) & 1);
}

// ---------------------------------------------------------------------------
// Prepass 1: RoPE + permute + tf32-round Q,K into [bh][l][pd] layout.
// ---------------------------------------------------------------------------
__global__ void rope_perm_kernel(const float* __restrict__ q,
                                 const float* __restrict__ k) {
    int idx = blockIdx.x * blockDim.x + threadIdx.x;   // float4 over [b][l][h][e4]
    const int N4 = BB * LL * HH * 16;
    if (idx >= N4) return;
    int e4  = idx & 15;
    int row = idx >> 4;            // (b*LL + l)*HH + h
    int h = row & 15;
    int bl = row >> 4;
    int l = bl & (LL - 1);
    int b = bl >> 11;
    float4 vq = ((const float4*)q)[idx];
    float4 vk = ((const float4*)k)[idx];
    if (e4 < 8) {
        float i0 = (float)(e4 * 2);
        const float NEG_L2 = -0.83048202372184058696f;  // -log2(10000)/16
        float s0, c0, s1, c1;
        sincosf((float)l * exp2f(i0 * NEG_L2), &s0, &c0);
        sincosf((float)l * exp2f((i0 + 1.0f) * NEG_L2), &s1, &c1);
        float4 o;
        o.x = c0 * vq.x - s0 * vq.y;  o.y = c0 * vq.y + s0 * vq.x;
        o.z = c1 * vq.z - s1 * vq.w;  o.w = c1 * vq.w + s1 * vq.z;
        vq = o;
        o.x = c0 * vk.x - s0 * vk.y;  o.y = c0 * vk.y + s0 * vk.x;
        o.z = c1 * vk.z - s1 * vk.w;  o.w = c1 * vk.w + s1 * vk.z;
        vk = o;
    }
    int e = e4 * 4;
    int p0 = permd(e);             // p(e+i) = p0 + i*4  (t = i within the quad)
    size_t base = ((size_t)(b * HH + h) * LL + l) * EE;
    float* qd = g_Qp + base;
    float* kd = g_Kp + base;
    qd[p0] = tfr(vq.x); qd[p0 + 4] = tfr(vq.y); qd[p0 + 8] = tfr(vq.z); qd[p0 + 12] = tfr(vq.w);
    kd[p0] = tfr(vk.x); kd[p0 + 4] = tfr(vk.y); kd[p0 + 8] = tfr(vk.z); kd[p0 + 12] = tfr(vk.w);
}

// ---------------------------------------------------------------------------
// Prepass 2: transpose V per (b,h,kt) 64x64 tile -> g_Vt[bh][d][kt*64 + pk(j)]
// ---------------------------------------------------------------------------
__global__ void vt_kernel(const float* __restrict__ v) {
    __shared__ float vs[64 * 65];
    const int kt = blockIdx.x, h = blockIdx.y, b = blockIdx.z;
    const int tid = threadIdx.x;
    const float* Vg = v + ((size_t)(b * LL + kt * 64) * HH + h) * EE;
    #pragma unroll
    for (int it = 0; it < 4; it++) {
        int i = it * 256 + tid;
        int j = i >> 4, e = (i & 15) * 4;
        float4 w = *(const float4*)(Vg + (size_t)j * (HH * EE) + e);
        vs[j * 65 + e + 0] = w.x; vs[j * 65 + e + 1] = w.y;
        vs[j * 65 + e + 2] = w.z; vs[j * 65 + e + 3] = w.w;
    }
    __syncthreads();
    float* Vd = g_Vt + (size_t)(b * HH + h) * EE * LL + kt * 64;
    #pragma unroll
    for (int it = 0; it < 16; it++) {
        int i = it * 256 + tid;
        int d = i >> 6, j = i & 63;
        Vd[(size_t)d * LL + permd(j)] = tfr(vs[j * 65 + d]);
    }
}

// ---------------------------------------------------------------------------
// Main attention: zero smem, zero barriers. 4 warps / CTA, 128 query rows.
// Warp w owns row bands {16w, 112-16w}  (local bands {16w, 48-16w}) so the
// per-tile triangular mask prunes exactly 6/16 (mb,nb) blocks per warp,
// identically for all warps.
// ---------------------------------------------------------------------------
__global__ __launch_bounds__(128)
void attn2(const float* __restrict__ bw, float* __restrict__ out) {
    const int tid  = threadIdx.x;
    const int lane = tid & 31;
    const int w    = tid >> 5;
    const int g    = lane >> 2;
    const int t    = lane & 3;
    const int qtb  = blockIdx.x;
    const int h    = blockIdx.y;
    const int b    = blockIdx.z;
    const int bh   = b * HH + h;
    const int l0   = qtb * 128;

    const int base0 = w * 16;            // rows [base0, base0+16), var qtb*2
    const int base1 = 112 - w * 16;      // rows [base1, base1+16), var qtb*2+1
    const int rl[2]  = { base0, base1 & 63 };
    const int nbm[2] = { (rl[0] >> 3) + 2, (rl[1] >> 3) + 2 };
    const int nbmx   = (nbm[0] > nbm[1]) ? nbm[0] : nbm[1];

    const float b2s = bw[HH + h] * LOG2E;
    const float b2d = bw[h] * LOG2E;

    // ---- persistent Q A-frags (direct LDG from permuted layout) ----
    const float* Qp = g_Qp + ((size_t)bh * LL + l0) * EE;
    uint32_t qa[2][8][4];
    #pragma unroll
    for (int mb = 0; mb < 2; mb++) {
        int rb = (mb ? base1 : base0) + g;
        #pragma unroll
        for (int kbp = 0; kbp < 4; kbp++) {
            uint4 x = *(const uint4*)(Qp + (size_t)rb * EE + kbp * 16 + t * 4);
            uint4 y = *(const uint4*)(Qp + (size_t)(rb + 8) * EE + kbp * 16 + t * 4);
            qa[mb][2 * kbp][0] = x.x;  qa[mb][2 * kbp][2] = x.y;
            qa[mb][2 * kbp + 1][0] = x.z;  qa[mb][2 * kbp + 1][2] = x.w;
            qa[mb][2 * kbp][1] = y.x;  qa[mb][2 * kbp][3] = y.y;
            qa[mb][2 * kbp + 1][1] = y.z;  qa[mb][2 * kbp + 1][3] = y.w;
        }
    }

    float oacc[2][8][4];
    #pragma unroll
    for (int mb = 0; mb < 2; mb++)
        #pragma unroll
        for (int db = 0; db < 8; db++)
            #pragma unroll
            for (int i = 0; i < 4; i++) oacc[mb][db][i] = 0.0f;
    float lsum[2][2] = {{0.0f, 0.0f}, {0.0f, 0.0f}};

    const int  src0 = (lane & ~3) + (t >> 1);
    const int  src1 = src0 + 2;
    const bool odd  = (t & 1);

    const float* Kp0 = g_Kp + (size_t)bh * LL * EE;
    const float* Vt0 = g_Vt + (size_t)bh * EE * LL;

    for (int kt = 0; kt < NKT; kt++) {
        const float* Kt = Kp0 + (size_t)kt * 64 * EE;
        const float* Vt = Vt0 + kt * 64;
        float bias[2];
        bias[0] = (kt == 2 * qtb)     ? b2s : b2d;
        bias[1] = (kt == 2 * qtb + 1) ? b2s : b2d;

        #pragma unroll
        for (int nbp = 0; nbp < 4; nbp++) {
            const int nb0 = 2 * nbp, nb1 = nb0 + 1;
            if (nb0 >= nbmx) continue;          // warp-uniform prune
            const bool a00 = nb0 < nbm[0], a01 = nb0 < nbm[1];
            const bool a10 = nb1 < nbm[0], a11 = nb1 < nbm[1];
            const bool kn1 = a10 | a11;         // nb0 always needed here

            // ---- K frags (direct LDG) ----
            uint4 kq0[4], kq1[4];
            #pragma unroll
            for (int kbp = 0; kbp < 4; kbp++)
                kq0[kbp] = *(const uint4*)(Kt + (size_t)(nb0 * 8 + g) * EE + kbp * 16 + t * 4);
            if (kn1) {
                #pragma unroll
                for (int kbp = 0; kbp < 4; kbp++)
                    kq1[kbp] = *(const uint4*)(Kt + (size_t)(nb1 * 8 + g) * EE + kbp * 16 + t * 4);
            }

            // ---- S = Q K^T ----
            float c[2][2][4];      // [nbi][mb][4]
            #pragma unroll
            for (int i = 0; i < 2; i++)
                #pragma unroll
                for (int j = 0; j < 2; j++)
                    #pragma unroll
                    for (int q_ = 0; q_ < 4; q_++) c[i][j][q_] = 0.0f;
            #pragma unroll
            for (int kbp = 0; kbp < 4; kbp++) {
                if (a00) { mma8(c[0][0], qa[0][2 * kbp], kq0[kbp].x, kq0[kbp].y);
                           mma8(c[0][0], qa[0][2 * kbp + 1], kq0[kbp].z, kq0[kbp].w); }
                if (a01) { mma8(c[0][1], qa[1][2 * kbp], kq0[kbp].x, kq0[kbp].y);
                           mma8(c[0][1], qa[1][2 * kbp + 1], kq0[kbp].z, kq0[kbp].w); }
                if (a10) { mma8(c[1][0], qa[0][2 * kbp], kq1[kbp].x, kq1[kbp].y);
                           mma8(c[1][0], qa[0][2 * kbp + 1], kq1[kbp].z, kq1[kbp].w); }
                if (a11) { mma8(c[1][1], qa[1][2 * kbp], kq1[kbp].x, kq1[kbp].y);
                           mma8(c[1][1], qa[1][2 * kbp + 1], kq1[kbp].z, kq1[kbp].w); }
            }

            // ---- softmax + P frag relayout (quad shuffles) ----
            uint32_t pa[2][2][4];
            #pragma unroll
            for (int nbi = 0; nbi < 2; nbi++) {
                const int nb = nb0 + nbi;
                const int c0i = nb * 8 + 2 * t, c1i = c0i + 1;
                #pragma unroll
                for (int mb = 0; mb < 2; mb++) {
                    const bool act = nbi ? (mb ? a11 : a10) : (mb ? a01 : a00);
                    if (!act) continue;
                    const int n0 = rl[mb] + g, n1 = n0 + 8;
                    float p0 = (c0i <= n0) ? ex2f(fmaf(c[nbi][mb][0], SCL2, bias[mb])) : 0.0f;
                    float p1 = (c1i <= n0) ? ex2f(fmaf(c[nbi][mb][1], SCL2, bias[mb])) : 0.0f;
                    float p2 = (c0i <= n1) ? ex2f(fmaf(c[nbi][mb][2], SCL2, bias[mb])) : 0.0f;
                    float p3 = (c1i <= n1) ? ex2f(fmaf(c[nbi][mb][3], SCL2, bias[mb])) : 0.0f;
                    lsum[mb][0] += p0 + p1;
                    lsum[mb][1] += p2 + p3;
                    uint32_t u0 = f2tf(p0), u1 = f2tf(p1), u2 = f2tf(p2), u3 = f2tf(p3);
                    uint32_t x0 = __shfl_sync(0xffffffffu, u0, src0);
                    uint32_t x1 = __shfl_sync(0xffffffffu, u1, src0);
                    pa[nbi][mb][0] = odd ? x1 : x0;
                    uint32_t y0 = __shfl_sync(0xffffffffu, u2, src0);
                    uint32_t y1 = __shfl_sync(0xffffffffu, u3, src0);
                    pa[nbi][mb][1] = odd ? y1 : y0;
                    uint32_t z0 = __shfl_sync(0xffffffffu, u0, src1);
                    uint32_t z1 = __shfl_sync(0xffffffffu, u1, src1);
                    pa[nbi][mb][2] = odd ? z1 : z0;
                    uint32_t w0 = __shfl_sync(0xffffffffu, u2, src1);
                    uint32_t w1 = __shfl_sync(0xffffffffu, u3, src1);
                    pa[nbi][mb][3] = odd ? w1 : w0;
                }
            }

            // ---- O += P V (V frags via direct LDG; x,y = nb0, z,w = nb1) ----
            #pragma unroll
            for (int db = 0; db < 8; db++) {
                uint4 vq = *(const uint4*)(Vt + (size_t)(db * 8 + g) * LL + nbp * 16 + t * 4);
                if (a00) mma8(oacc[0][db], pa[0][0], vq.x, vq.y);
                if (a01) mma8(oacc[1][db], pa[0][1], vq.x, vq.y);
                if (a10) mma8(oacc[0][db], pa[1][0], vq.z, vq.w);
                if (a11) mma8(oacc[1][db], pa[1][1], vq.z, vq.w);
            }
        }
    }

    // ---- reduce row sums across quad, normalize, store ----
    #pragma unroll
    for (int mb = 0; mb < 2; mb++)
        #pragma unroll
        for (int i = 0; i < 2; i++) {
            float v = lsum[mb][i];
            v += __shfl_xor_sync(0xffffffffu, v, 1);
            v += __shfl_xor_sync(0xffffffffu, v, 2);
            lsum[mb][i] = 1.0f / v;
        }

    #pragma unroll
    for (int mb = 0; mb < 2; mb++) {
        int r0 = l0 + (mb ? base1 : base0) + g;
        #pragma unroll
        for (int db = 0; db < 8; db++) {
            float2 v0;
            v0.x = oacc[mb][db][0] * lsum[mb][0];
            v0.y = oacc[mb][db][1] * lsum[mb][0];
            *(float2*)(out + (((size_t)(b * LL + r0)) * HH + h) * EE + db * 8 + 2 * t) = v0;
            float2 v1;
            v1.x = oacc[mb][db][2] * lsum[mb][1];
            v1.y = oacc[mb][db][3] * lsum[mb][1];
            *(float2*)(out + (((size_t)(b * LL + r0 + 8)) * HH + h) * EE + db * 8 + 2 * t) = v1;
        }
    }
}

// ---------------------------------------------------------------------------
extern "C" void kernel_launch(void* const* d_in, const int* in_sizes, int n_in,
                              void* d_out, int out_size) {
    const float* q  = (const float*)d_in[0];
    const float* k  = (const float*)d_in[1];
    const float* v  = (const float*)d_in[2];
    const float* bw = (const float*)d_in[3];
    float* out = (float*)d_out;

    const int N4 = BB * LL * HH * 16;
    rope_perm_kernel<<<(N4 + 255) / 256, 256>>>(q, k);
    vt_kernel<<<dim3(NKT, HH, BB), 256>>>(v);

    dim3 grid(LL / 128, HH, BB);
    attn2<<<grid, 128>>>(bw, out);
}